// round 6
// baseline (speedup 1.0000x reference)
#include <cuda_runtime.h>
#include <cuda_bf16.h>

#define IMG_H 512
#define IMG_W 512
#define IMG_HW (IMG_H * IMG_W)
#define OUT_H 510
#define OUT_W 510
#define BLOCK 256
#define NWARP (BLOCK / 32)

#define TS_W 32                 // windows per block, horizontal
#define TS_H 8                  // windows per block, vertical
#define TILE_W (TS_W + 2)       // 34
#define TILE_H (TS_H + 2)       // 10
#define GRID_X ((OUT_W + TS_W - 1) / TS_W)   // 16
#define GRID_Y ((OUT_H + TS_H - 1) / TS_H)   // 64
#define NBLK (GRID_X * GRID_Y)               // 1024

// Scratch for deterministic fused reduction (no device allocation allowed).
__device__ double g_partials[NBLK];
__device__ unsigned int g_ticket = 0;

__global__ void __launch_bounds__(BLOCK) ml_tile_kernel(
    const float* __restrict__ tgt, const float* __restrict__ sty,
    float* __restrict__ out)
{
    __shared__ float tile[6][TILE_H][TILE_W];   // 8160 B

    const int tid = threadIdx.x;
    const int bx = blockIdx.x, by = blockIdx.y;
    const int c0 = bx * TS_W, r0 = by * TS_H;

    // ---- Cooperative coalesced tile load (12 LDG per thread) ----
    #pragma unroll
    for (int a = 0; a < 6; a++) {
        const float* src = (a < 3) ? (tgt + a * IMG_HW) : (sty + (a - 3) * IMG_HW);
        #pragma unroll
        for (int base = 0; base < TILE_H * TILE_W; base += BLOCK) {
            const int idx = base + tid;
            if (idx < TILE_H * TILE_W) {
                const int tr = idx / TILE_W;
                const int tc = idx - tr * TILE_W;
                const int gr = r0 + tr, gc = c0 + tc;
                float v = 0.0f;
                if (gr < IMG_H && gc < IMG_W) v = __ldg(src + gr * IMG_W + gc);
                tile[a][tr][tc] = v;
            }
        }
    }
    __syncthreads();

    // ---- One window per thread, streaming statistics from smem ----
    const int wr = tid >> 5;        // 0..7
    const int wc = tid & 31;        // 0..31
    const int row = r0 + wr, col = c0 + wc;

    float contrib = 0.0f;
    if (row < OUT_H && col < OUT_W) {
        const float inv9 = 1.0f / 9.0f;
        const float eps9 = 1e-7f / 9.0f;

        // Accumulators: target sums (3), target Gram (6),
        // style sums (3), style sq-sums (3), cross matrix Y[ch][cv] (9).
        float s0 = 0.f, s1 = 0.f, s2 = 0.f;
        float g00 = 0.f, g01 = 0.f, g02 = 0.f, g11 = 0.f, g12 = 0.f, g22 = 0.f;
        float sv0 = 0.f, sv1 = 0.f, sv2 = 0.f;
        float qv0 = 0.f, qv1 = 0.f, qv2 = 0.f;
        float Y00 = 0.f, Y01 = 0.f, Y02 = 0.f;
        float Y10 = 0.f, Y11 = 0.f, Y12 = 0.f;
        float Y20 = 0.f, Y21 = 0.f, Y22 = 0.f;

        #pragma unroll
        for (int dr = 0; dr < 3; dr++) {
            #pragma unroll
            for (int dc = 0; dc < 3; dc++) {
                const float a  = tile[0][wr + dr][wc + dc];
                const float b  = tile[1][wr + dr][wc + dc];
                const float d  = tile[2][wr + dr][wc + dc];
                const float v0 = tile[3][wr + dr][wc + dc];
                const float v1 = tile[4][wr + dr][wc + dc];
                const float v2 = tile[5][wr + dr][wc + dc];
                s0 += a; s1 += b; s2 += d;
                g00 += a * a; g01 += a * b; g02 += a * d;
                g11 += b * b; g12 += b * d; g22 += d * d;
                sv0 += v0; sv1 += v1; sv2 += v2;
                qv0 += v0 * v0; qv1 += v1 * v1; qv2 += v2 * v2;
                Y00 += a * v0; Y01 += a * v1; Y02 += a * v2;
                Y10 += b * v0; Y11 += b * v1; Y12 += b * v2;
                Y20 += d * v0; Y21 += d * v1; Y22 += d * v2;
            }
        }

        const float mu0 = s0 * inv9, mu1 = s1 * inv9, mu2 = s2 * inv9;

        // Covariance + eps/9 * I
        g00 = g00 * inv9 - mu0 * mu0 + eps9;
        g01 = g01 * inv9 - mu0 * mu1;
        g02 = g02 * inv9 - mu0 * mu2;
        g11 = g11 * inv9 - mu1 * mu1 + eps9;
        g12 = g12 * inv9 - mu1 * mu2;
        g22 = g22 * inv9 - mu2 * mu2 + eps9;

        // Adjugate (symmetric) and determinant.
        const float adj00 = g11 * g22 - g12 * g12;
        const float adj01 = g02 * g12 - g01 * g22;
        const float adj02 = g01 * g12 - g02 * g11;
        const float adj11 = g00 * g22 - g02 * g02;
        const float adj12 = g01 * g02 - g00 * g12;
        const float adj22 = g00 * g11 - g01 * g01;
        const float det = g00 * adj00 + g01 * adj01 + g02 * adj02;
        const float invdet = 1.0f / det;

        // Per style channel cv: y_ch = Y[ch][cv] - mu_ch * sv_cv
        // score = q - (s^2 + y^T adj y * invdet) / 9
        #pragma unroll
        for (int cv = 0; cv < 3; cv++) {
            const float s = (cv == 0) ? sv0 : (cv == 1) ? sv1 : sv2;
            const float q = (cv == 0) ? qv0 : (cv == 1) ? qv1 : qv2;
            const float y0 = ((cv == 0) ? Y00 : (cv == 1) ? Y01 : Y02) - mu0 * s;
            const float y1 = ((cv == 0) ? Y10 : (cv == 1) ? Y11 : Y12) - mu1 * s;
            const float y2 = ((cv == 0) ? Y20 : (cv == 1) ? Y21 : Y22) - mu2 * s;
            const float quad = adj00 * y0 * y0 + adj11 * y1 * y1 + adj22 * y2 * y2
                             + 2.0f * (adj01 * y0 * y1 + adj02 * y0 * y2 + adj12 * y1 * y2);
            contrib += q - (s * s + quad * invdet) * inv9;
        }
    }

    // ---- Block reduction: warp shuffles (deterministic fixed tree) ----
    double acc = (double)contrib;
    #pragma unroll
    for (int off = 16; off > 0; off >>= 1)
        acc += __shfl_down_sync(0xFFFFFFFFu, acc, off);

    __shared__ double warp_sums[NWARP];
    const int lane = tid & 31;
    const int wid = tid >> 5;
    if (lane == 0) warp_sums[wid] = acc;
    __syncthreads();

    __shared__ bool is_last;
    if (tid == 0) {
        double bsum = 0.0;
        #pragma unroll
        for (int i = 0; i < NWARP; i++) bsum += warp_sums[i];
        const int bid = by * GRID_X + bx;
        g_partials[bid] = bsum;
        unsigned int t;
        asm volatile("atom.release.gpu.global.add.u32 %0, [%1], %2;"
                     : "=r"(t) : "l"(&g_ticket), "r"(1u) : "memory");
        is_last = (t == (unsigned)(NBLK - 1));
    }
    __syncthreads();

    // ---- Last block performs the final deterministic reduction ----
    if (is_last) {
        double a = 0.0;
        for (int i = tid; i < NBLK; i += BLOCK) {
            double v;
            asm volatile("ld.acquire.gpu.global.f64 %0, [%1];"
                         : "=d"(v) : "l"(&g_partials[i]) : "memory");
            a += v;
        }
        #pragma unroll
        for (int off = 16; off > 0; off >>= 1)
            a += __shfl_down_sync(0xFFFFFFFFu, a, off);
        if (lane == 0) warp_sums[wid] = a;
        __syncthreads();
        if (tid == 0) {
            double tot = 0.0;
            #pragma unroll
            for (int i = 0; i < NWARP; i++) tot += warp_sums[i];
            out[0] = (float)tot;
            g_ticket = 0;   // reset for next graph replay
        }
    }
}

extern "C" void kernel_launch(void* const* d_in, const int* in_sizes, int n_in,
                              void* d_out, int out_size)
{
    const float* tgt = (const float*)d_in[0];   // target  (3, 512, 512) fp32
    const float* sty = (const float*)d_in[1];   // style   (3, 512, 512) fp32
    float* out = (float*)d_out;

    dim3 grid(GRID_X, GRID_Y);
    ml_tile_kernel<<<grid, BLOCK>>>(tgt, sty, out);
}

// round 7
// speedup vs baseline: 1.6875x; 1.6875x over previous
#include <cuda_runtime.h>
#include <cuda_bf16.h>

#define IMG_H 512
#define IMG_W 512
#define IMG_HW (IMG_H * IMG_W)
#define OUT_H 510
#define OUT_W 510
#define WIN_PER_WARP 30
#define SEGS 17                              // 17 * 30 = 510 windows per row
#define NWU (SEGS * OUT_H)                   // 8670 warp-units
#define BLOCK 256
#define NWARP (BLOCK / 32)
#define NBLK ((NWU + NWARP - 1) / NWARP)     // 1084

// Scratch for deterministic fused reduction (no device allocation allowed).
__device__ double g_partials[NBLK];
__device__ unsigned int g_ticket = 0;

__device__ __forceinline__ float win3(float x) {
    // window stat = colstat(l) + colstat(l+1) + colstat(l+2)
    const float x1 = __shfl_down_sync(0xFFFFFFFFu, x, 1);
    const float x2 = __shfl_down_sync(0xFFFFFFFFu, x, 2);
    return x + x1 + x2;
}

__global__ void __launch_bounds__(BLOCK) ml_col_kernel(
    const float* __restrict__ tgt, const float* __restrict__ sty,
    float* __restrict__ out)
{
    const int tid = threadIdx.x;
    const int lane = tid & 31;
    const int wid = tid >> 5;
    const int wu = blockIdx.x * NWARP + wid;

    float contrib = 0.0f;
    if (wu < NWU) {
        const int row = wu / SEGS;
        const int seg = wu - row * SEGS;
        const int col = seg * WIN_PER_WARP + lane;     // 0..511, always in-bounds
        const int base = row * IMG_W + col;

        // ---- 18 coalesced loads: 3 rows x 3 channels x {target, style} ----
        float a0r0 = __ldg(tgt + 0 * IMG_HW + base);
        float a0r1 = __ldg(tgt + 0 * IMG_HW + base + IMG_W);
        float a0r2 = __ldg(tgt + 0 * IMG_HW + base + 2 * IMG_W);
        float a1r0 = __ldg(tgt + 1 * IMG_HW + base);
        float a1r1 = __ldg(tgt + 1 * IMG_HW + base + IMG_W);
        float a1r2 = __ldg(tgt + 1 * IMG_HW + base + 2 * IMG_W);
        float a2r0 = __ldg(tgt + 2 * IMG_HW + base);
        float a2r1 = __ldg(tgt + 2 * IMG_HW + base + IMG_W);
        float a2r2 = __ldg(tgt + 2 * IMG_HW + base + 2 * IMG_W);
        float v0r0 = __ldg(sty + 0 * IMG_HW + base);
        float v0r1 = __ldg(sty + 0 * IMG_HW + base + IMG_W);
        float v0r2 = __ldg(sty + 0 * IMG_HW + base + 2 * IMG_W);
        float v1r0 = __ldg(sty + 1 * IMG_HW + base);
        float v1r1 = __ldg(sty + 1 * IMG_HW + base + IMG_W);
        float v1r2 = __ldg(sty + 1 * IMG_HW + base + 2 * IMG_W);
        float v2r0 = __ldg(sty + 2 * IMG_HW + base);
        float v2r1 = __ldg(sty + 2 * IMG_HW + base + IMG_W);
        float v2r2 = __ldg(sty + 2 * IMG_HW + base + 2 * IMG_W);

        // ---- Per-column statistics (24 values) ----
        const float cs0 = a0r0 + a0r1 + a0r2;
        const float cs1 = a1r0 + a1r1 + a1r2;
        const float cs2 = a2r0 + a2r1 + a2r2;
        const float cg00 = a0r0 * a0r0 + a0r1 * a0r1 + a0r2 * a0r2;
        const float cg01 = a0r0 * a1r0 + a0r1 * a1r1 + a0r2 * a1r2;
        const float cg02 = a0r0 * a2r0 + a0r1 * a2r1 + a0r2 * a2r2;
        const float cg11 = a1r0 * a1r0 + a1r1 * a1r1 + a1r2 * a1r2;
        const float cg12 = a1r0 * a2r0 + a1r1 * a2r1 + a1r2 * a2r2;
        const float cg22 = a2r0 * a2r0 + a2r1 * a2r1 + a2r2 * a2r2;
        const float csv0 = v0r0 + v0r1 + v0r2;
        const float csv1 = v1r0 + v1r1 + v1r2;
        const float csv2 = v2r0 + v2r1 + v2r2;
        const float cqv0 = v0r0 * v0r0 + v0r1 * v0r1 + v0r2 * v0r2;
        const float cqv1 = v1r0 * v1r0 + v1r1 * v1r1 + v1r2 * v1r2;
        const float cqv2 = v2r0 * v2r0 + v2r1 * v2r1 + v2r2 * v2r2;
        const float cY00 = a0r0 * v0r0 + a0r1 * v0r1 + a0r2 * v0r2;
        const float cY01 = a0r0 * v1r0 + a0r1 * v1r1 + a0r2 * v1r2;
        const float cY02 = a0r0 * v2r0 + a0r1 * v2r1 + a0r2 * v2r2;
        const float cY10 = a1r0 * v0r0 + a1r1 * v0r1 + a1r2 * v0r2;
        const float cY11 = a1r0 * v1r0 + a1r1 * v1r1 + a1r2 * v1r2;
        const float cY12 = a1r0 * v2r0 + a1r1 * v2r1 + a1r2 * v2r2;
        const float cY20 = a2r0 * v0r0 + a2r1 * v0r1 + a2r2 * v0r2;
        const float cY21 = a2r0 * v1r0 + a2r1 * v1r1 + a2r2 * v1r2;
        const float cY22 = a2r0 * v2r0 + a2r1 * v2r1 + a2r2 * v2r2;

        // ---- Window statistics via warp shuffles (lanes 0..29 valid) ----
        const float s0 = win3(cs0), s1 = win3(cs1), s2 = win3(cs2);
        float g00 = win3(cg00), g01 = win3(cg01), g02 = win3(cg02);
        float g11 = win3(cg11), g12 = win3(cg12), g22 = win3(cg22);
        const float sv0 = win3(csv0), sv1 = win3(csv1), sv2 = win3(csv2);
        const float qv0 = win3(cqv0), qv1 = win3(cqv1), qv2 = win3(cqv2);
        const float Y00 = win3(cY00), Y01 = win3(cY01), Y02 = win3(cY02);
        const float Y10 = win3(cY10), Y11 = win3(cY11), Y12 = win3(cY12);
        const float Y20 = win3(cY20), Y21 = win3(cY21), Y22 = win3(cY22);

        if (lane < WIN_PER_WARP) {
            const float inv9 = 1.0f / 9.0f;
            const float eps9 = 1e-7f / 9.0f;
            const float mu0 = s0 * inv9, mu1 = s1 * inv9, mu2 = s2 * inv9;

            g00 = g00 * inv9 - mu0 * mu0 + eps9;
            g01 = g01 * inv9 - mu0 * mu1;
            g02 = g02 * inv9 - mu0 * mu2;
            g11 = g11 * inv9 - mu1 * mu1 + eps9;
            g12 = g12 * inv9 - mu1 * mu2;
            g22 = g22 * inv9 - mu2 * mu2 + eps9;

            const float adj00 = g11 * g22 - g12 * g12;
            const float adj01 = g02 * g12 - g01 * g22;
            const float adj02 = g01 * g12 - g02 * g11;
            const float adj11 = g00 * g22 - g02 * g02;
            const float adj12 = g01 * g02 - g00 * g12;
            const float adj22 = g00 * g11 - g01 * g01;
            const float det = g00 * adj00 + g01 * adj01 + g02 * adj02;
            const float invdet = 1.0f / det;

            // ch 0
            {
                const float s = sv0, q = qv0;
                const float y0 = Y00 - mu0 * s, y1 = Y10 - mu1 * s, y2 = Y20 - mu2 * s;
                const float quad = adj00 * y0 * y0 + adj11 * y1 * y1 + adj22 * y2 * y2
                                 + 2.0f * (adj01 * y0 * y1 + adj02 * y0 * y2 + adj12 * y1 * y2);
                contrib += q - (s * s + quad * invdet) * inv9;
            }
            // ch 1
            {
                const float s = sv1, q = qv1;
                const float y0 = Y01 - mu0 * s, y1 = Y11 - mu1 * s, y2 = Y21 - mu2 * s;
                const float quad = adj00 * y0 * y0 + adj11 * y1 * y1 + adj22 * y2 * y2
                                 + 2.0f * (adj01 * y0 * y1 + adj02 * y0 * y2 + adj12 * y1 * y2);
                contrib += q - (s * s + quad * invdet) * inv9;
            }
            // ch 2
            {
                const float s = sv2, q = qv2;
                const float y0 = Y02 - mu0 * s, y1 = Y12 - mu1 * s, y2 = Y22 - mu2 * s;
                const float quad = adj00 * y0 * y0 + adj11 * y1 * y1 + adj22 * y2 * y2
                                 + 2.0f * (adj01 * y0 * y1 + adj02 * y0 * y2 + adj12 * y1 * y2);
                contrib += q - (s * s + quad * invdet) * inv9;
            }
        }
    }

    // ---- Block reduction: warp shuffles (deterministic fixed tree) ----
    double acc = (double)contrib;
    #pragma unroll
    for (int off = 16; off > 0; off >>= 1)
        acc += __shfl_down_sync(0xFFFFFFFFu, acc, off);

    __shared__ double warp_sums[NWARP];
    if (lane == 0) warp_sums[wid] = acc;
    __syncthreads();

    __shared__ bool is_last;
    if (tid == 0) {
        double bsum = 0.0;
        #pragma unroll
        for (int i = 0; i < NWARP; i++) bsum += warp_sums[i];
        g_partials[blockIdx.x] = bsum;
        unsigned int t;
        asm volatile("atom.release.gpu.global.add.u32 %0, [%1], %2;"
                     : "=r"(t) : "l"(&g_ticket), "r"(1u) : "memory");
        is_last = (t == (unsigned)(NBLK - 1));
    }
    __syncthreads();

    // ---- Last block performs the final deterministic reduction ----
    if (is_last) {
        double a = 0.0;
        for (int i = tid; i < NBLK; i += BLOCK) {
            double v;
            asm volatile("ld.acquire.gpu.global.f64 %0, [%1];"
                         : "=d"(v) : "l"(&g_partials[i]) : "memory");
            a += v;
        }
        #pragma unroll
        for (int off = 16; off > 0; off >>= 1)
            a += __shfl_down_sync(0xFFFFFFFFu, a, off);
        if (lane == 0) warp_sums[wid] = a;
        __syncthreads();
        if (tid == 0) {
            double tot = 0.0;
            #pragma unroll
            for (int i = 0; i < NWARP; i++) tot += warp_sums[i];
            out[0] = (float)tot;
            g_ticket = 0;   // reset for next graph replay
        }
    }
}

extern "C" void kernel_launch(void* const* d_in, const int* in_sizes, int n_in,
                              void* d_out, int out_size)
{
    const float* tgt = (const float*)d_in[0];   // target  (3, 512, 512) fp32
    const float* sty = (const float*)d_in[1];   // style   (3, 512, 512) fp32
    float* out = (float*)d_out;

    ml_col_kernel<<<NBLK, BLOCK>>>(tgt, sty, out);
}